// round 11
// baseline (speedup 1.0000x reference)
#include <cuda_runtime.h>

#define THREADS   256
#define ELEMS     2                      // elements per thread in scan tile
#define TILE      (THREADS * ELEMS)      // 512 (scan tile = first columns)
#define COLS      32768
// fill region = 32256 floats = 4032 x v8 (32B); 4032 = 15*256 + 192
#define FILL_V8_ITERS 15
#define FILL_V8_REM   192                // threads with one extra v8 store
#define FULLMASK  0xffffffffu

// Row-wise inclusive prefix product (cumprod along dim=1) for [1024, 32768].
// One CTA per row.
//
// Inputs are U(0,1): the running product underflows to exactly +0.0f well
// inside the first 512 columns (surviving past col 512 is an 18-sigma
// event), and 0 * finite = +0 exactly, so every output past the scan tile
// is exactly +0. Even in the impossible survival case, the fallback below
// rescans the row properly — the shortcut is performance-only.
//
// R2-R10 established the ~5.7 TB/s path-independent write-stream ceiling
// for the 128 MB output; the champion (R10) sits on the byte floor. This
// round tests the last untried cell of the store matrix: 256-bit stores
// WITH the streaming hint (st.global.cs.v8.f32). R4 tested width without
// .cs (regressed); R5 showed .cs alone buys ~2us of steady-state wall.
//
//   1. issue tile-0 load (memory starts immediately)
//   2. streaming 256-bit zero-fill of cols [512, 32768)
//   3. scan tile-0, store cols [0, 512), compute carry
//   4. if carry != 0 (general-correctness fallback, unreachable for this
//      data): barrier, then scan tiles 1..63 properly, overwriting zeros.

// 256-bit streaming store of 8 zero floats (sm_100a STG.256, evict-first).
__device__ __forceinline__ void stcs256_zero(float* p)
{
    asm volatile(
        "st.global.cs.v8.f32 [%0], {%1, %1, %1, %1, %1, %1, %1, %1};"
        :: "l"(p), "f"(0.0f) : "memory");
}

__global__ __launch_bounds__(THREADS, 8)
void cumprod_rows_kernel(const float* __restrict__ x,
                         float* __restrict__ out,
                         int cols)
{
    __shared__ float s_warp[8];

    const int row  = blockIdx.x;
    const int tid  = threadIdx.x;
    const int lane = tid & 31;
    const int warp = tid >> 5;

    const float* __restrict__ xr   = x   + (size_t)row * (size_t)cols;
    float*       __restrict__ orow = out + (size_t)row * (size_t)cols;

    // ---- 1. start tile-0 load ----
    const int base0 = tid * ELEMS;
    const float2 a = *reinterpret_cast<const float2*>(xr + base0);

    // ---- 2. streaming 256-bit zero-fill of [TILE, cols) ----
    {
        float* p = orow + TILE + tid * 8;          // 32B-aligned
        #pragma unroll
        for (int k = 0; k < FILL_V8_ITERS; ++k) {
            stcs256_zero(p + k * (THREADS * 8));
        }
        if (tid < FILL_V8_REM) {
            stcs256_zero(p + FILL_V8_ITERS * (THREADS * 8));
        }
    }

    // ---- 3. scan tile 0 ----
    float p0 = a.x;
    float p1 = p0 * a.y;

    float v = p1;
    #pragma unroll
    for (int off = 1; off < 32; off <<= 1) {
        float n = __shfl_up_sync(FULLMASK, v, off);
        if (lane >= off) v *= n;
    }
    if (lane == 31) s_warp[warp] = v;
    __syncthreads();

    if (warp == 0) {
        float w = (lane < 8) ? s_warp[lane] : 1.0f;
        #pragma unroll
        for (int off = 1; off < 8; off <<= 1) {
            float n = __shfl_up_sync(FULLMASK, w, off);
            if (lane >= off) w *= n;
        }
        if (lane < 8) s_warp[lane] = w;
    }
    __syncthreads();

    {
        const float warp_excl = (warp == 0) ? 1.0f : s_warp[warp - 1];
        float lane_excl = __shfl_up_sync(FULLMASK, v, 1);
        if (lane == 0) lane_excl = 1.0f;
        const float prefix = warp_excl * lane_excl;

        float2 o0 = make_float2(prefix * p0, prefix * p1);
        __stcs(reinterpret_cast<float2*>(orow + base0), o0);
    }

    float carry = s_warp[7];            // block total of tile 0 (uniform)

    // ---- 4. fallback: carry survived tile 0 (unreachable for U(0,1)) ----
    if (carry != 0.0f) {
        __syncthreads();                // order zero stores vs. rescan stores
        const int ntiles = cols / TILE;
        for (int t = 1; t < ntiles; ++t) {
            const int base = t * TILE + tid * ELEMS;
            const float2 c = *reinterpret_cast<const float2*>(xr + base);

            float q0 = c.x;
            float q1 = q0 * c.y;

            float u = q1;
            #pragma unroll
            for (int off = 1; off < 32; off <<= 1) {
                float n = __shfl_up_sync(FULLMASK, u, off);
                if (lane >= off) u *= n;
            }
            if (lane == 31) s_warp[warp] = u;
            __syncthreads();

            if (warp == 0) {
                float w = (lane < 8) ? s_warp[lane] : 1.0f;
                #pragma unroll
                for (int off = 1; off < 8; off <<= 1) {
                    float n = __shfl_up_sync(FULLMASK, w, off);
                    if (lane >= off) w *= n;
                }
                if (lane < 8) s_warp[lane] = w;
            }
            __syncthreads();

            const float warp_excl = (warp == 0) ? 1.0f : s_warp[warp - 1];
            float lane_excl = __shfl_up_sync(FULLMASK, u, 1);
            if (lane == 0) lane_excl = 1.0f;
            const float prefix = carry * warp_excl * lane_excl;

            float2 o0 = make_float2(prefix * q0, prefix * q1);
            *reinterpret_cast<float2*>(orow + base) = o0;

            carry *= s_warp[7];
            __syncthreads();
        }
    }
}

extern "C" void kernel_launch(void* const* d_in, const int* in_sizes, int n_in,
                              void* d_out, int out_size)
{
    const float* x   = (const float*)d_in[0];
    float*       out = (float*)d_out;

    const int cols = COLS;
    const int rows = out_size / cols;   // 1024

    cumprod_rows_kernel<<<rows, THREADS>>>(x, out, cols);
}

// round 12
// speedup vs baseline: 1.0532x; 1.0532x over previous
#include <cuda_runtime.h>

#define THREADS   256
#define ELEMS     2                      // elements per thread in scan tile
#define TILE      (THREADS * ELEMS)      // 512 (scan tile = first columns)
#define COLS      32768
// fill region = 32256 floats = 8064 float4; 8064 = 31*256 + 128
#define FILL_ITERS 31
#define FILL_REM   128                   // threads with one extra float4
#define FULLMASK  0xffffffffu

// Row-wise inclusive prefix product (cumprod along dim=1) for [1024, 32768].
// One CTA per row.  FINAL CONFIGURATION (revert to R10 champion).
//
// Inputs are U(0,1): the running product underflows to exactly +0.0f well
// inside the first 512 columns (E[log2 prod] = -739, sd 32.6; surviving past
// col 512 is an 18-sigma event), and 0 * finite = +0 exactly, so every
// output past the scan tile is exactly +0. Even in the impossible survival
// case, the fallback below rescans the row properly — the shortcut is
// performance-only, never correctness.
//
// Session findings (R2-R11):
//  - The 128 MB output stream is pinned at ~5.7 TB/s on EVERY write path
//    (STG.128/256 x default/.cs, TMA bulk, memset engine, graph fork-join):
//    the path-independent L2-transit/write-drain ceiling for a >L2 stream.
//  - 128-bit stores WITH the streaming (.cs, evict-first) hint give the
//    best steady-state wall; 256-bit stores regress wall ~1.3us at equal
//    kernel time regardless of policy.
//  - Kernel time 22.5-22.9us == 130 MB / 5.7 TB/s byte floor; remaining
//    wall-kernel gap is fixed harness/replay overhead.
//
//   1. issue tile-0 load (memory starts immediately)
//   2. streaming zero-fill of cols [512, 32768) (31.5 x STG.128.cs/thread)
//   3. scan tile-0, store cols [0, 512), compute carry
//   4. if carry != 0 (general-correctness fallback, unreachable for this
//      data): barrier, then scan tiles 1..63 properly, overwriting zeros.
__global__ __launch_bounds__(THREADS, 8)
void cumprod_rows_kernel(const float* __restrict__ x,
                         float* __restrict__ out,
                         int cols)
{
    __shared__ float s_warp[8];

    const int row  = blockIdx.x;
    const int tid  = threadIdx.x;
    const int lane = tid & 31;
    const int warp = tid >> 5;

    const float* __restrict__ xr   = x   + (size_t)row * (size_t)cols;
    float*       __restrict__ orow = out + (size_t)row * (size_t)cols;

    // ---- 1. start tile-0 load ----
    const int base0 = tid * ELEMS;
    const float2 a = *reinterpret_cast<const float2*>(xr + base0);

    // ---- 2. streaming zero-fill of [TILE, cols) ----
    {
        const float4 z = make_float4(0.f, 0.f, 0.f, 0.f);
        float4* p = reinterpret_cast<float4*>(orow + TILE) + tid;
        #pragma unroll
        for (int k = 0; k < FILL_ITERS; ++k) {
            __stcs(p + k * THREADS, z);
        }
        if (tid < FILL_REM) {
            __stcs(p + FILL_ITERS * THREADS, z);
        }
    }

    // ---- 3. scan tile 0 ----
    float p0 = a.x;
    float p1 = p0 * a.y;

    float v = p1;
    #pragma unroll
    for (int off = 1; off < 32; off <<= 1) {
        float n = __shfl_up_sync(FULLMASK, v, off);
        if (lane >= off) v *= n;
    }
    if (lane == 31) s_warp[warp] = v;
    __syncthreads();

    if (warp == 0) {
        float w = (lane < 8) ? s_warp[lane] : 1.0f;
        #pragma unroll
        for (int off = 1; off < 8; off <<= 1) {
            float n = __shfl_up_sync(FULLMASK, w, off);
            if (lane >= off) w *= n;
        }
        if (lane < 8) s_warp[lane] = w;
    }
    __syncthreads();

    {
        const float warp_excl = (warp == 0) ? 1.0f : s_warp[warp - 1];
        float lane_excl = __shfl_up_sync(FULLMASK, v, 1);
        if (lane == 0) lane_excl = 1.0f;
        const float prefix = warp_excl * lane_excl;

        float2 o0 = make_float2(prefix * p0, prefix * p1);
        __stcs(reinterpret_cast<float2*>(orow + base0), o0);
    }

    float carry = s_warp[7];            // block total of tile 0 (uniform)

    // ---- 4. fallback: carry survived tile 0 (unreachable for U(0,1)) ----
    if (carry != 0.0f) {
        __syncthreads();                // order zero stores vs. rescan stores
        const int ntiles = cols / TILE;
        for (int t = 1; t < ntiles; ++t) {
            const int base = t * TILE + tid * ELEMS;
            const float2 c = *reinterpret_cast<const float2*>(xr + base);

            float q0 = c.x;
            float q1 = q0 * c.y;

            float u = q1;
            #pragma unroll
            for (int off = 1; off < 32; off <<= 1) {
                float n = __shfl_up_sync(FULLMASK, u, off);
                if (lane >= off) u *= n;
            }
            if (lane == 31) s_warp[warp] = u;
            __syncthreads();

            if (warp == 0) {
                float w = (lane < 8) ? s_warp[lane] : 1.0f;
                #pragma unroll
                for (int off = 1; off < 8; off <<= 1) {
                    float n = __shfl_up_sync(FULLMASK, w, off);
                    if (lane >= off) w *= n;
                }
                if (lane < 8) s_warp[lane] = w;
            }
            __syncthreads();

            const float warp_excl = (warp == 0) ? 1.0f : s_warp[warp - 1];
            float lane_excl = __shfl_up_sync(FULLMASK, u, 1);
            if (lane == 0) lane_excl = 1.0f;
            const float prefix = carry * warp_excl * lane_excl;

            float2 o0 = make_float2(prefix * q0, prefix * q1);
            *reinterpret_cast<float2*>(orow + base) = o0;

            carry *= s_warp[7];
            __syncthreads();
        }
    }
}

extern "C" void kernel_launch(void* const* d_in, const int* in_sizes, int n_in,
                              void* d_out, int out_size)
{
    const float* x   = (const float*)d_in[0];
    float*       out = (float*)d_out;

    const int cols = COLS;
    const int rows = out_size / cols;   // 1024

    cumprod_rows_kernel<<<rows, THREADS>>>(x, out, cols);
}